// round 1
// baseline (speedup 1.0000x reference)
#include <cuda_runtime.h>
#include <float.h>

// Problem constants
#define NTOK 32768   // 512 * 64 tokens
#define DIMD 256     // feature dim
#define KVOC 8192    // codebook size

// Tiling
#define MT 128       // tokens per CTA
#define NT 128       // codewords per n-tile
#define KC 32        // k-chunk
#define PAD 132      // smem row stride (floats), multiple of 4 for float4 loads

// Scratch (no allocations allowed)
__device__ int   g_idx[NTOK];
__device__ float g_vnorm[KVOC];

// ---------------------------------------------------------------------------
// Kernel 1: half squared norms of codebook rows: g_vnorm[k] = 0.5 * ||v_k||^2
// ---------------------------------------------------------------------------
__global__ void vnorm_kernel(const float* __restrict__ vocab) {
    int row  = blockIdx.x * (blockDim.x >> 5) + (threadIdx.x >> 5);
    int lane = threadIdx.x & 31;
    if (row >= KVOC) return;
    const float4* v = (const float4*)(vocab + (size_t)row * DIMD);
    float s = 0.f;
    #pragma unroll
    for (int d = lane; d < DIMD / 4; d += 32) {
        float4 x = v[d];
        s += x.x * x.x + x.y * x.y + x.z * x.z + x.w * x.w;
    }
    #pragma unroll
    for (int o = 16; o; o >>= 1) s += __shfl_xor_sync(0xffffffffu, s, o);
    if (lane == 0) g_vnorm[row] = 0.5f * s;
}

// ---------------------------------------------------------------------------
// Kernel 2: fused GEMM + running argmin.
// score(t, k) = 0.5*||v_k||^2 - x_t . v_k   (argmin identical to L2 argmin)
// Each CTA owns 128 tokens, loops over all 8192 codewords in 128-wide tiles.
// ---------------------------------------------------------------------------
__global__ __launch_bounds__(256, 2)
void argmin_kernel(const float* __restrict__ seq, const float* __restrict__ vocab) {
    __shared__ float As[KC][PAD];   // [k][m]
    __shared__ float Bs[KC][PAD];   // [k][n]

    const int tid = threadIdx.x;
    const int tm  = tid >> 4;   // 0..15  -> rows tm*8 .. tm*8+7
    const int tn  = tid & 15;   // 0..15  -> cols tn*8 .. tn*8+7
    const int m0  = blockIdx.x * MT;

    const int lk = tid & 31;    // k index for cooperative loads
    const int lm = tid >> 5;    // 0..7 row base for cooperative loads

    float minv[8];
    int   mini[8];
    #pragma unroll
    for (int i = 0; i < 8; i++) { minv[i] = FLT_MAX; mini[i] = 0; }

    for (int n0 = 0; n0 < KVOC; n0 += NT) {
        float acc[8][8];
        #pragma unroll
        for (int i = 0; i < 8; i++)
            #pragma unroll
            for (int j = 0; j < 8; j++) acc[i][j] = 0.f;

        for (int kc = 0; kc < DIMD; kc += KC) {
            __syncthreads();
            // Load A chunk (k-major): As[k][m] = seq[(m0+m)*D + kc + k]
            #pragma unroll
            for (int m = lm; m < MT; m += 8)
                As[lk][m] = seq[(size_t)(m0 + m) * DIMD + kc + lk];
            // Load B chunk (k-major): Bs[k][n] = vocab[(n0+n)*D + kc + k]
            #pragma unroll
            for (int n = lm; n < NT; n += 8)
                Bs[lk][n] = vocab[(size_t)(n0 + n) * DIMD + kc + lk];
            __syncthreads();

            #pragma unroll 8
            for (int k = 0; k < KC; k++) {
                float4 a0 = *(const float4*)&As[k][tm * 8];
                float4 a1 = *(const float4*)&As[k][tm * 8 + 4];
                float4 b0 = *(const float4*)&Bs[k][tn * 8];
                float4 b1 = *(const float4*)&Bs[k][tn * 8 + 4];
                float a[8] = {a0.x, a0.y, a0.z, a0.w, a1.x, a1.y, a1.z, a1.w};
                float b[8] = {b0.x, b0.y, b0.z, b0.w, b1.x, b1.y, b1.z, b1.w};
                #pragma unroll
                for (int i = 0; i < 8; i++)
                    #pragma unroll
                    for (int j = 0; j < 8; j++)
                        acc[i][j] += a[i] * b[j];
            }
        }

        // Epilogue: fold this n-tile into the running argmin (scan n ascending
        // with strict < so ties resolve to the lowest index, like jnp.argmin).
        #pragma unroll
        for (int j = 0; j < 8; j++) {
            int n = n0 + tn * 8 + j;
            float vn = g_vnorm[n];
            #pragma unroll
            for (int i = 0; i < 8; i++) {
                float sc = vn - acc[i][j];
                if (sc < minv[i]) { minv[i] = sc; mini[i] = n; }
            }
        }
    }

    // Reduce argmin across the 16 tn-threads (contiguous 16-lane groups).
    #pragma unroll
    for (int off = 8; off; off >>= 1) {
        #pragma unroll
        for (int i = 0; i < 8; i++) {
            float ov = __shfl_down_sync(0xffffffffu, minv[i], off, 16);
            int   oi = __shfl_down_sync(0xffffffffu, mini[i], off, 16);
            if (ov < minv[i] || (ov == minv[i] && oi < mini[i])) {
                minv[i] = ov; mini[i] = oi;
            }
        }
    }
    if (tn == 0) {
        #pragma unroll
        for (int i = 0; i < 8; i++)
            g_idx[m0 + tm * 8 + i] = mini[i];
    }
}

// ---------------------------------------------------------------------------
// Kernel 3: gather quantized vectors + write indices (as float) after them.
// ---------------------------------------------------------------------------
__global__ void gather_kernel(const float* __restrict__ vocab,
                              float* __restrict__ out, int write_idx) {
    int token = blockIdx.x * 4 + (threadIdx.x >> 6);
    int l     = threadIdx.x & 63;          // 64 float4 = 256 floats per token
    int idx   = g_idx[token];
    const float4* src = (const float4*)(vocab + (size_t)idx * DIMD);
    float4*       dst = (float4*)(out + (size_t)token * DIMD);
    dst[l] = src[l];
    if (write_idx && l == 0)
        out[(size_t)NTOK * DIMD + token] = (float)idx;
}

// ---------------------------------------------------------------------------
extern "C" void kernel_launch(void* const* d_in, const int* in_sizes, int n_in,
                              void* d_out, int out_size) {
    const float* seq   = (const float*)d_in[0];   // [512, 64, 256] f32
    const float* vocab = (const float*)d_in[1];   // [8192, 256]    f32
    float* out = (float*)d_out;

    // Output = quantized vectors [T*D] followed (if room) by indices as f32 [T].
    int write_idx = (out_size >= NTOK * DIMD + NTOK) ? 1 : 0;

    vnorm_kernel<<<KVOC / 8, 256>>>(vocab);
    argmin_kernel<<<NTOK / MT, 256>>>(seq, vocab);
    gather_kernel<<<NTOK / 4, 256>>>(vocab, out, write_idx);
}